// round 15
// baseline (speedup 1.0000x reference)
#include <cuda_runtime.h>
#include <cuda_fp16.h>
#include <cstdint>
#include <math.h>

#define DMODEL 1024
#define NHEADS 16
#define HD 64
#define BATCH 4
#define SEQ 2048
#define ROWS (BATCH * SEQ)   /* 8192 */
#define NQKV (3 * DMODEL)    /* 3072 */

// softmax scale folded with log2(e) (base-2 softmax)
#define SC (0.125f * 1.44269504088896340736f)

// ---------------------------------------------------------------------------
// Scratch (allocation-free __device__ globals), fp16 operands
// ---------------------------------------------------------------------------
__device__ __align__(256) __half g_xh[(size_t)ROWS * DMODEL];        // x
__device__ __align__(256) __half g_qwh[(size_t)NQKV * DMODEL];       // qkv_w
__device__ __align__(256) __half g_owh[(size_t)DMODEL * DMODEL];     // out_w
__device__ __align__(256) __half g_ch[(size_t)ROWS * DMODEL];        // ctx
// per-head attention operands, written by fused QKV epilogue
__device__ __align__(256) __half g_Qh[(size_t)ROWS * DMODEL];        // Q [bh][s][64]
__device__ __align__(256) __half g_Kh[(size_t)ROWS * DMODEL];        // K [bh][s][64]
__device__ __align__(256) __half g_Vth[(size_t)ROWS * DMODEL];       // V^T [bh][d][s]

// ---------------------------------------------------------------------------
// helpers
// ---------------------------------------------------------------------------
__device__ __forceinline__ uint32_t smem_u32(const void* p) {
    return (uint32_t)__cvta_generic_to_shared(p);
}

__device__ __forceinline__ uint32_t pack2(float a, float b) {
    __half2 h = __floats2half2_rn(a, b);
    return *reinterpret_cast<uint32_t*>(&h);
}

__device__ __forceinline__ float2 h2f2(uint32_t u) {
    __half2 h = *reinterpret_cast<__half2*>(&u);
    return __half22float2(h);
}

__device__ __forceinline__ float ex2(float x) {
    float y;
    asm("ex2.approx.ftz.f32 %0, %1;" : "=f"(y) : "f"(x));
    return y;
}

#define LDSM4(r, addr) \
    asm volatile("ldmatrix.sync.aligned.m8n8.x4.shared.b16 {%0,%1,%2,%3}, [%4];" \
                 : "=r"((r)[0]), "=r"((r)[1]), "=r"((r)[2]), "=r"((r)[3]) : "r"(addr))

#define MMA16816(d, a, b0, b1) \
    asm volatile("mma.sync.aligned.m16n8k16.row.col.f32.f16.f16.f32 " \
                 "{%0,%1,%2,%3}, {%4,%5,%6,%7}, {%8,%9}, {%0,%1,%2,%3};" \
                 : "+f"((d)[0]), "+f"((d)[1]), "+f"((d)[2]), "+f"((d)[3]) \
                 : "r"((a)[0]), "r"((a)[1]), "r"((a)[2]), "r"((a)[3]), \
                   "r"(b0), "r"(b1))

// f16-accumulate MMA (double rate): D,C in 2 x b32 (4 halves)
#define MMA16816H(d, a, b0, b1) \
    asm volatile("mma.sync.aligned.m16n8k16.row.col.f16.f16.f16.f16 " \
                 "{%0,%1}, {%2,%3,%4,%5}, {%6,%7}, {%0,%1};" \
                 : "+r"((d)[0]), "+r"((d)[1]) \
                 : "r"((a)[0]), "r"((a)[1]), "r"((a)[2]), "r"((a)[3]), \
                   "r"(b0), "r"(b1))

#define CP_ASYNC16(dst, src) \
    asm volatile("cp.async.cg.shared.global [%0], [%1], 16;" :: "r"(dst), "l"(src))
#define CP_COMMIT() asm volatile("cp.async.commit_group;" ::: "memory")
#define CP_WAIT1()  asm volatile("cp.async.wait_group 1;" ::: "memory")
#define CP_WAIT0()  asm volatile("cp.async.wait_group 0;" ::: "memory")

// ---------------------------------------------------------------------------
// fp32 -> fp16 convert (4-wide)
// ---------------------------------------------------------------------------
__global__ void cvt_kernel(const float4* __restrict__ in, uint2* __restrict__ hi, int n4) {
    int i = blockIdx.x * blockDim.x + threadIdx.x;
    if (i >= n4) return;
    float4 v = in[i];
    uint2 uh;
    uh.x = pack2(v.x, v.y);
    uh.y = pack2(v.z, v.w);
    hi[i] = uh;
}

// ---------------------------------------------------------------------------
// Tensor-core GEMM via mma.sync, pure fp16 operands, fp32 accumulate.
// C = A*B^T + bias.  BM=BN=128, BK=64 (one barrier per 64-k slab),
// 256 thr, warp tile 64x32, 3-stage cp.async pipeline, 2 CTAs/SM.
// QKV_EPI: write Q/K per-head fp16 and V transposed fp16.
// ---------------------------------------------------------------------------
#define BK 64
#define PITCHB 144                      /* 128B data + 16B pad, conflict-free */
#define ARR_BYTES (128 * PITCHB)        /* 18432 */
#define STG_BYTES (2 * ARR_BYTES)       /* 36864: A, B */
#define GEMM_SMEM (3 * STG_BYTES)       /* 110592 (>= epilogue 67584) */
#define CPITCH 132                      /* C staging pitch (floats) */

__device__ __forceinline__ void load_stage(
    uint32_t sb, int k0, int t,
    const __half* __restrict__ A, const __half* __restrict__ B,
    int m0, int n0, int K)
{
#pragma unroll
    for (int i = 0; i < 8; i++) {
        int idx = t + i * 256;          // 0..2047
        int arr = idx >> 10;            // 0:A 1:B
        int u   = idx & 1023;
        int row = u >> 3;               // 0..127
        int c   = u & 7;                // 16B chunk 0..7 (64 halves per row)
        const __half* base = arr ? B : A;
        int grow = (arr ? n0 : m0) + row;
        const __half* src = base + (size_t)grow * K + k0 + c * 8;
        uint32_t dst = sb + arr * ARR_BYTES + row * PITCHB + c * 16;
        CP_ASYNC16(dst, src);
    }
}

template <bool QKV_EPI>
__global__ void __launch_bounds__(256, 2) gemm_tc(
    const __half* __restrict__ A, const __half* __restrict__ B,
    const float* __restrict__ bias, float* __restrict__ C, int N, int K)
{
    extern __shared__ char dyn_smem[];
    const int t = threadIdx.x, wid = t >> 5, lane = t & 31;
    const int m0 = blockIdx.y * 128, n0 = blockIdx.x * 128;
    const int KT = K / BK;

    const uint32_t sbase = smem_u32(dyn_smem);
    const int wm = (wid >> 2) * 64;
    const int wn = (wid & 3) * 32;

    const int lmat = lane >> 3, lr = lane & 7;
    const uint32_t aOff = (uint32_t)((wm + (lmat & 1) * 8 + lr) * PITCHB + (lmat >> 1) * 16);
    const uint32_t bOff = (uint32_t)((wn + (lmat >> 1) * 8 + lr) * PITCHB + (lmat & 1) * 16);

    float acc[4][4][4];
#pragma unroll
    for (int i = 0; i < 4; i++)
#pragma unroll
        for (int j = 0; j < 4; j++)
#pragma unroll
            for (int r = 0; r < 4; r++) acc[i][j][r] = 0.f;

    load_stage(sbase + 0 * STG_BYTES, 0,  t, A, B, m0, n0, K);
    CP_COMMIT();
    load_stage(sbase + 1 * STG_BYTES, BK, t, A, B, m0, n0, K);
    CP_COMMIT();

    for (int kt = 0; kt < KT; kt++) {
        CP_WAIT1();
        __syncthreads();
        if (kt + 2 < KT)
            load_stage(sbase + ((kt + 2) % 3) * STG_BYTES, (kt + 2) * BK,
                       t, A, B, m0, n0, K);
        CP_COMMIT();

        const uint32_t sb = sbase + (kt % 3) * STG_BYTES;
#pragma unroll
        for (int ks = 0; ks < 4; ks++) {
            uint32_t ah[4][4], bh[2][4];
            const uint32_t kb = ks * 32;
#pragma unroll
            for (int mt = 0; mt < 4; mt++)
                LDSM4(ah[mt], sb + 0 * ARR_BYTES + aOff + mt * (16 * PITCHB) + kb);
#pragma unroll
            for (int j = 0; j < 2; j++)
                LDSM4(bh[j], sb + 1 * ARR_BYTES + bOff + j * (16 * PITCHB) + kb);
#pragma unroll
            for (int mt = 0; mt < 4; mt++)
#pragma unroll
                for (int nt = 0; nt < 4; nt++)
                    MMA16816(acc[mt][nt], ah[mt],
                             bh[nt >> 1][(nt & 1) * 2], bh[nt >> 1][(nt & 1) * 2 + 1]);
        }
    }
    CP_WAIT0();
    __syncthreads();

    const int g = lane >> 2, tg = lane & 3;

    if (!QKV_EPI) {
        float* Cs = (float*)dyn_smem;      // [128][CPITCH]
#pragma unroll
        for (int mt = 0; mt < 4; mt++)
#pragma unroll
            for (int nt = 0; nt < 4; nt++) {
                int r0 = wm + mt * 16 + g;
                int cc = wn + nt * 8 + tg * 2;
                Cs[r0 * CPITCH + cc]       = acc[mt][nt][0];
                Cs[r0 * CPITCH + cc + 1]   = acc[mt][nt][1];
                Cs[(r0 + 8) * CPITCH + cc]     = acc[mt][nt][2];
                Cs[(r0 + 8) * CPITCH + cc + 1] = acc[mt][nt][3];
            }
        __syncthreads();

        const int q = t & 31;
        const int rb = t >> 5;
        float4 bv = *(const float4*)(bias + n0 + q * 4);
#pragma unroll
        for (int i = 0; i < 16; i++) {
            int row = rb + i * 8;
            float4 v = *(const float4*)&Cs[row * CPITCH + q * 4];
            v.x += bv.x; v.y += bv.y; v.z += bv.z; v.w += bv.w;
            *(float4*)(C + (size_t)(m0 + row) * N + n0 + q * 4) = v;
        }
    } else {
        // fused QKV epilogue: bias + fp16 cvt + per-head scatter
        float* Cs = (float*)dyn_smem;      // [128][CPITCH]
        float bv[4][2];
#pragma unroll
        for (int nt = 0; nt < 4; nt++) {
            int gc = n0 + wn + nt * 8 + tg * 2;
            bv[nt][0] = bias[gc];
            bv[nt][1] = bias[gc + 1];
        }
#pragma unroll
        for (int mt = 0; mt < 4; mt++)
#pragma unroll
            for (int nt = 0; nt < 4; nt++) {
                int r0 = wm + mt * 16 + g;
                int cc = wn + nt * 8 + tg * 2;
                Cs[r0 * CPITCH + cc]       = acc[mt][nt][0] + bv[nt][0];
                Cs[r0 * CPITCH + cc + 1]   = acc[mt][nt][1] + bv[nt][1];
                Cs[(r0 + 8) * CPITCH + cc]     = acc[mt][nt][2] + bv[nt][0];
                Cs[(r0 + 8) * CPITCH + cc + 1] = acc[mt][nt][3] + bv[nt][1];
            }
        __syncthreads();

        const int b = m0 >> 11;
        const int sb0 = m0 & 2047;
        const int h0 = (n0 & 1023) >> 6;

        if (n0 < 2048) {
            // Q or K: [bh][s][64] row-major, fp16
            __half* Dh = (n0 < 1024) ? g_Qh : g_Kh;
            const int u = t & 63;
            const int h = h0 + (u >> 5);
            const int d0 = (u * 2) & 63;
            const int rofs = t >> 6;
#pragma unroll
            for (int p = 0; p < 32; p++) {
                int row = p * 4 + rofs;
                float v0 = Cs[row * CPITCH + 2 * u];
                float v1 = Cs[row * CPITCH + 2 * u + 1];
                size_t dst = ((size_t)(b * NHEADS + h) * SEQ + sb0 + row) * HD + d0;
                *(uint32_t*)(Dh + dst) = pack2(v0, v1);
            }
        } else {
            // V: transposed [bh][d][s], fp16
            const int w = t >> 5;
            const int l = t & 31;
#pragma unroll
            for (int i = 0; i < 16; i++) {
                int c = w * 16 + i;
                int h = h0 + (c >> 6);
                int d = c & 63;
#pragma unroll
                for (int qq = 0; qq < 2; qq++) {
                    int r = 2 * (l + 32 * qq);
                    float v0 = Cs[r * CPITCH + c];
                    float v1 = Cs[(r + 1) * CPITCH + c];
                    size_t dst = ((size_t)(b * NHEADS + h) * HD + d) * SEQ + sb0 + r;
                    *(uint32_t*)(g_Vth + dst) = pack2(v0, v1);
                }
            }
        }
    }
}

// ---------------------------------------------------------------------------
// Tensor-core flash attention.  QK f16-acc (2x rate), PV fp32-acc.
// Deferred-PV pipeline with DOUBLE-BUFFERED P fragments.
// Tiles: 0 prologue (buf0); pairs (1,2)...(29,30); tail 31 (buf1).
// Q tile 128, K/V tiles 64.  Grid (SEQ/128, NHEADS, BATCH), 256 threads
// (8 warps, 16 q-rows each), 2 CTAs/SM.
// ---------------------------------------------------------------------------
#define APB 144
#define QARR (128 * APB)                /* 18432 */
#define AARR (64 * APB)                 /* 9216 */
#define ATTN_SMEM (QARR + 3 * AARR + 4 * AARR)  /* 82944 */

__global__ void __launch_bounds__(256, 2) attn_tc(
    const __half* __restrict__ Qh,
    const __half* __restrict__ Kh,
    const __half* __restrict__ Vth)
{
    extern __shared__ char dyn_smem[];
    const int t = threadIdx.x, wid = t >> 5, lane = t & 31;
    const int qt = blockIdx.x, h = blockIdx.y, b = blockIdx.z;
    const int bh = b * NHEADS + h;
    const int q0 = qt * 128;

    const uint32_t sQh = smem_u32(dyn_smem);
    const uint32_t sK  = sQh + QARR;          // 3 buffers
    const uint32_t sV  = sK + 3 * AARR;       // 4 buffers

    const size_t qkBase = (size_t)bh * SEQ * HD;
    const size_t vBase  = (size_t)bh * HD * SEQ;

    // Q tile: 128 rows x 8 chunks = 1024 chunks
#pragma unroll
    for (int i = 0; i < 4; i++) {
        int idx = t + i * 256;
        int row = idx >> 3, ch = idx & 7;
        const __half* src = Qh + qkBase + (size_t)(q0 + row) * HD + ch * 8;
        CP_ASYNC16(sQh + row * APB + ch * 16, src);
    }
// tile j: K -> buf j%3, V -> buf j%4
#define LOAD_KV_TILE(j) do { \
    int kk0 = (j) * 64; \
    uint32_t kbuf = sK + ((j) % 3) * AARR; \
    uint32_t vbuf = sV + ((j) % 4) * AARR; \
    _Pragma("unroll") \
    for (int i = 0; i < 4; i++) { \
        int idx = t + i * 256; \
        int arr = idx >> 9; \
        int u = idx & 511, row = u >> 3, ch = u & 7; \
        const __half* src; uint32_t dbuf; \
        if (arr == 0) { src = Kh  + qkBase + (size_t)(kk0 + row) * HD + ch * 8; dbuf = kbuf; } \
        else          { src = Vth + vBase + (size_t)row * SEQ + kk0 + ch * 8; dbuf = vbuf; } \
        CP_ASYNC16(dbuf + row * APB + ch * 16, src); \
    } \
} while (0)

    LOAD_KV_TILE(0);
    CP_COMMIT();
    LOAD_KV_TILE(1);
    CP_COMMIT();

    const int wm = wid * 16;
    const int lmat = lane >> 3, lr = lane & 7;
    const uint32_t aOff = (uint32_t)((wm + (lmat & 1) * 8 + lr) * APB + (lmat >> 1) * 16);
    const uint32_t bOff = (uint32_t)(((lmat >> 1) * 8 + lr) * APB + (lmat & 1) * 16);
    const int g = lane >> 2, tg = lane & 3;

    float O[8][4];
#pragma unroll
    for (int i = 0; i < 8; i++)
#pragma unroll
        for (int j = 0; j < 4; j++) O[i][j] = 0.f;
    float m0r = -1e30f, m1r = -1e30f, l0 = 0.f, l1 = 0.f;
    float cp0[2], cp1[2];                // double-buffered rescale factors
    uint32_t ph[2][16];                  // double-buffered packed P (fp16)
    uint32_t Sh[16];                     // f16x2 QK accumulators

// compute S(f16) = Q K(kt)^T
#define QK_TILE(kt) do { \
    const uint32_t sKb = sK + ((kt) % 3) * AARR; \
    _Pragma("unroll") \
    for (int r = 0; r < 16; r++) Sh[r] = 0u; \
    _Pragma("unroll") \
    for (int kc = 0; kc < 4; kc++) { \
        uint32_t qh[4]; \
        LDSM4(qh, sQh + aOff + kc * 32); \
        _Pragma("unroll") \
        for (int j = 0; j < 4; j++) { \
            uint32_t kh[4]; \
            LDSM4(kh, sKb + j * (16 * APB) + bOff + kc * 32); \
            MMA16816H(&Sh[j * 4 + 0], qh, kh[0], kh[1]); \
            MMA16816H(&Sh[j * 4 + 2], qh, kh[2], kh[3]); \
        } \
    } \
} while (0)

// online softmax on Sh -> writes ph[pb], cp0[pb], cp1[pb]
#define SOFTMAX_PACK(pb) do { \
    float rmax0 = -1e30f, rmax1 = -1e30f; \
    _Pragma("unroll") \
    for (int r = 0; r < 16; r += 2) { \
        float2 a = h2f2(Sh[r]); \
        float2 bb = h2f2(Sh[r + 1]); \
        rmax0 = fmaxf(rmax0, fmaxf(a.x, a.y)); \
        rmax1 = fmaxf(rmax1, fmaxf(bb.x, bb.y)); \
    } \
    _Pragma("unroll") \
    for (int d = 1; d <= 2; d <<= 1) { \
        rmax0 = fmaxf(rmax0, __shfl_xor_sync(0xffffffffu, rmax0, d)); \
        rmax1 = fmaxf(rmax1, __shfl_xor_sync(0xffffffffu, rmax1, d)); \
    } \
    float mn0 = fmaxf(m0r, rmax0), mn1 = fmaxf(m1r, rmax1); \
    float ms0 = mn0 * SC, ms1 = mn1 * SC; \
    float sum0 = 0.f, sum1 = 0.f; \
    _Pragma("unroll") \
    for (int r = 0; r < 16; r += 2) { \
        float2 a = h2f2(Sh[r]); \
        float2 bb = h2f2(Sh[r + 1]); \
        float p0 = ex2(fmaf(a.x, SC, -ms0)); \
        float p1 = ex2(fmaf(a.y, SC, -ms0)); \
        float p2 = ex2(fmaf(bb.x, SC, -ms1)); \
        float p3 = ex2(fmaf(bb.y, SC, -ms1)); \
        sum0 += p0 + p1; \
        sum1 += p2 + p3; \
        ph[pb][r] = pack2(p0, p1); \
        ph[pb][r + 1] = pack2(p2, p3); \
    } \
    _Pragma("unroll") \
    for (int d = 1; d <= 2; d <<= 1) { \
        sum0 += __shfl_xor_sync(0xffffffffu, sum0, d); \
        sum1 += __shfl_xor_sync(0xffffffffu, sum1, d); \
    } \
    cp0[pb] = ex2(SC * (m0r - mn0)); \
    cp1[pb] = ex2(SC * (m1r - mn1)); \
    l0 = l0 * cp0[pb] + sum0; \
    l1 = l1 * cp1[pb] + sum1; \
    m0r = mn0; m1r = mn1; \
} while (0)

// O = O*c[pb] + P(ph[pb]) * V(tile vj)   (fp32 accumulate)
#define RESCALE_PV(vj, pb) do { \
    const uint32_t sVb = sV + ((vj) % 4) * AARR; \
    float c0v = cp0[pb], c1v = cp1[pb]; \
    _Pragma("unroll") \
    for (int i = 0; i < 8; i++) { \
        O[i][0] *= c0v; O[i][1] *= c0v; \
        O[i][2] *= c1v; O[i][3] *= c1v; \
    } \
    _Pragma("unroll") \
    for (int kg = 0; kg < 4; kg++) { \
        _Pragma("unroll") \
        for (int dn = 0; dn < 4; dn++) { \
            uint32_t vh[4]; \
            LDSM4(vh, sVb + dn * (16 * APB) + bOff + kg * 32); \
            MMA16816(O[2 * dn],     &ph[pb][kg * 4], vh[0], vh[1]); \
            MMA16816(O[2 * dn + 1], &ph[pb][kg * 4], vh[2], vh[3]); \
        } \
    } \
} while (0)

    const int NKT = SEQ / 64;   /* 32 */

    // ---- tile 0: QK + softmax only (packs into buf 0) ----
    CP_WAIT1();
    __syncthreads();
    LOAD_KV_TILE(2);
    CP_COMMIT();
    QK_TILE(0);
    SOFTMAX_PACK(0);

    // ---- main loop: pairs (kt, kt+1) = tiles 1..30 (15 pairs) ----
    for (int kt = 1; kt < NKT - 1; kt += 2) {
        CP_WAIT1();
        __syncthreads();
        if (kt + 2 < NKT) {
            LOAD_KV_TILE(kt + 2);
        }
        CP_COMMIT();
        QK_TILE(kt);
        RESCALE_PV(kt - 1, 0);
        SOFTMAX_PACK(1);

        CP_WAIT1();
        __syncthreads();
        if (kt + 3 < NKT) {
            LOAD_KV_TILE(kt + 3);
        }
        CP_COMMIT();
        QK_TILE(kt + 1);
        RESCALE_PV(kt, 1);
        SOFTMAX_PACK(0);
    }

    // ---- tail: tile NKT-1 = 31 (packs into buf 1) ----
    CP_WAIT1();
    __syncthreads();
    CP_COMMIT();
    QK_TILE(NKT - 1);
    RESCALE_PV(NKT - 2, 0);
    SOFTMAX_PACK(1);

    // ---- epilogue: final pending PV (tile 31, buf 1) ----
    RESCALE_PV(NKT - 1, 1);

    float inv0 = 1.0f / l0, inv1 = 1.0f / l1;
    int r0 = b * SEQ + q0 + wm + g;
    int r1 = r0 + 8;
#pragma unroll
    for (int ot = 0; ot < 8; ot++) {
        int col = h * HD + ot * 8 + tg * 2;
        *(uint32_t*)(g_ch + (size_t)r0 * DMODEL + col) =
            pack2(O[ot][0] * inv0, O[ot][1] * inv0);
        *(uint32_t*)(g_ch + (size_t)r1 * DMODEL + col) =
            pack2(O[ot][2] * inv1, O[ot][3] * inv1);
    }
}

extern "C" void kernel_launch(void* const* d_in, const int* in_sizes, int n_in,
                              void* d_out, int out_size)
{
    const float* x     = (const float*)d_in[0];
    const float* qkv_w = (const float*)d_in[1];
    const float* qkv_b = (const float*)d_in[2];
    const float* out_w = (const float*)d_in[3];
    const float* out_b = (const float*)d_in[4];
    float* out = (float*)d_out;

    void *p_xh, *p_qwh, *p_owh, *p_ch, *p_Qh, *p_Kh, *p_Vth;
    cudaGetSymbolAddress(&p_xh, g_xh);
    cudaGetSymbolAddress(&p_qwh, g_qwh);
    cudaGetSymbolAddress(&p_owh, g_owh);
    cudaGetSymbolAddress(&p_ch, g_ch);
    cudaGetSymbolAddress(&p_Qh, g_Qh);
    cudaGetSymbolAddress(&p_Kh, g_Kh);
    cudaGetSymbolAddress(&p_Vth, g_Vth);

    cudaFuncSetAttribute(gemm_tc<false>, cudaFuncAttributeMaxDynamicSharedMemorySize,
                         GEMM_SMEM);
    cudaFuncSetAttribute(gemm_tc<true>, cudaFuncAttributeMaxDynamicSharedMemorySize,
                         GEMM_SMEM);
    cudaFuncSetAttribute(attn_tc, cudaFuncAttributeMaxDynamicSharedMemorySize,
                         ATTN_SMEM);

    // convert inputs to fp16
    {
        int n4 = ROWS * DMODEL / 4;
        cvt_kernel<<<(n4 + 255) / 256, 256>>>((const float4*)x, (uint2*)p_xh, n4);
        n4 = NQKV * DMODEL / 4;
        cvt_kernel<<<(n4 + 255) / 256, 256>>>((const float4*)qkv_w, (uint2*)p_qwh, n4);
        n4 = DMODEL * DMODEL / 4;
        cvt_kernel<<<(n4 + 255) / 256, 256>>>((const float4*)out_w, (uint2*)p_owh, n4);
    }

    // 1) QKV projection with fused per-head scatter epilogue
    gemm_tc<true><<<dim3(NQKV / 128, ROWS / 128), 256, GEMM_SMEM>>>(
        (const __half*)p_xh, (const __half*)p_qwh,
        qkv_b, nullptr, NQKV, DMODEL);

    // 2) tensor-core flash attention -> ctx (fp16)
    attn_tc<<<dim3(SEQ / 128, NHEADS, BATCH), 256, ATTN_SMEM>>>(
        (const __half*)p_Qh, (const __half*)p_Kh, (const __half*)p_Vth);

    // 3) output projection
    gemm_tc<false><<<dim3(DMODEL / 128, ROWS / 128), 256, GEMM_SMEM>>>(
        (const __half*)p_ch, (const __half*)p_owh,
        out_b, out, DMODEL, DMODEL);
}

// round 16
// speedup vs baseline: 1.0008x; 1.0008x over previous
#include <cuda_runtime.h>
#include <cuda_fp16.h>
#include <cstdint>
#include <math.h>

#define DMODEL 1024
#define NHEADS 16
#define HD 64
#define BATCH 4
#define SEQ 2048
#define ROWS (BATCH * SEQ)   /* 8192 */
#define NQKV (3 * DMODEL)    /* 3072 */

// softmax scale folded with log2(e) (base-2 softmax)
#define SC (0.125f * 1.44269504088896340736f)

// ---------------------------------------------------------------------------
// Scratch (allocation-free __device__ globals), fp16 operands
// ---------------------------------------------------------------------------
__device__ __align__(256) __half g_xh[(size_t)ROWS * DMODEL];        // x
__device__ __align__(256) __half g_qwh[(size_t)NQKV * DMODEL];       // qkv_w
__device__ __align__(256) __half g_owh[(size_t)DMODEL * DMODEL];     // out_w
__device__ __align__(256) __half g_ch[(size_t)ROWS * DMODEL];        // ctx
// per-head attention operands, written by fused QKV epilogue
__device__ __align__(256) __half g_Qh[(size_t)ROWS * DMODEL];        // Q [bh][s][64]
__device__ __align__(256) __half g_Kh[(size_t)ROWS * DMODEL];        // K [bh][s][64]
__device__ __align__(256) __half g_Vth[(size_t)ROWS * DMODEL];       // V^T [bh][d][s]

// ---------------------------------------------------------------------------
// helpers
// ---------------------------------------------------------------------------
__device__ __forceinline__ uint32_t smem_u32(const void* p) {
    return (uint32_t)__cvta_generic_to_shared(p);
}

__device__ __forceinline__ uint32_t pack2(float a, float b) {
    __half2 h = __floats2half2_rn(a, b);
    return *reinterpret_cast<uint32_t*>(&h);
}

__device__ __forceinline__ float2 h2f2(uint32_t u) {
    __half2 h = *reinterpret_cast<__half2*>(&u);
    return __half22float2(h);
}

__device__ __forceinline__ float ex2(float x) {
    float y;
    asm("ex2.approx.ftz.f32 %0, %1;" : "=f"(y) : "f"(x));
    return y;
}

#define LDSM4(r, addr) \
    asm volatile("ldmatrix.sync.aligned.m8n8.x4.shared.b16 {%0,%1,%2,%3}, [%4];" \
                 : "=r"((r)[0]), "=r"((r)[1]), "=r"((r)[2]), "=r"((r)[3]) : "r"(addr))

#define MMA16816(d, a, b0, b1) \
    asm volatile("mma.sync.aligned.m16n8k16.row.col.f32.f16.f16.f32 " \
                 "{%0,%1,%2,%3}, {%4,%5,%6,%7}, {%8,%9}, {%0,%1,%2,%3};" \
                 : "+f"((d)[0]), "+f"((d)[1]), "+f"((d)[2]), "+f"((d)[3]) \
                 : "r"((a)[0]), "r"((a)[1]), "r"((a)[2]), "r"((a)[3]), \
                   "r"(b0), "r"(b1))

// f16-accumulate MMA (double rate): D,C in 2 x b32 (4 halves)
#define MMA16816H(d, a, b0, b1) \
    asm volatile("mma.sync.aligned.m16n8k16.row.col.f16.f16.f16.f16 " \
                 "{%0,%1}, {%2,%3,%4,%5}, {%6,%7}, {%0,%1};" \
                 : "+r"((d)[0]), "+r"((d)[1]) \
                 : "r"((a)[0]), "r"((a)[1]), "r"((a)[2]), "r"((a)[3]), \
                   "r"(b0), "r"(b1))

#define CP_ASYNC16(dst, src) \
    asm volatile("cp.async.cg.shared.global [%0], [%1], 16;" :: "r"(dst), "l"(src))
#define CP_COMMIT() asm volatile("cp.async.commit_group;" ::: "memory")
#define CP_WAIT1()  asm volatile("cp.async.wait_group 1;" ::: "memory")
#define CP_WAIT0()  asm volatile("cp.async.wait_group 0;" ::: "memory")

// ---------------------------------------------------------------------------
// fp32 -> fp16 convert (4-wide)
// ---------------------------------------------------------------------------
__global__ void cvt_kernel(const float4* __restrict__ in, uint2* __restrict__ hi, int n4) {
    int i = blockIdx.x * blockDim.x + threadIdx.x;
    if (i >= n4) return;
    float4 v = in[i];
    uint2 uh;
    uh.x = pack2(v.x, v.y);
    uh.y = pack2(v.z, v.w);
    hi[i] = uh;
}

// ---------------------------------------------------------------------------
// Tensor-core GEMM via mma.sync, pure fp16 operands, fp32 accumulate.
// C = A*B^T + bias.  BM=BN=128, BK=64 (one barrier per 64-k slab),
// 256 thr, warp tile 64x32, 3-stage cp.async pipeline, 2 CTAs/SM.
// QKV_EPI: write Q/K per-head fp16 and V transposed fp16.
// ---------------------------------------------------------------------------
#define BK 64
#define PITCHB 144                      /* 128B data + 16B pad, conflict-free */
#define ARR_BYTES (128 * PITCHB)        /* 18432 */
#define STG_BYTES (2 * ARR_BYTES)       /* 36864: A, B */
#define GEMM_SMEM (3 * STG_BYTES)       /* 110592 (>= epilogue 67584) */
#define CPITCH 132                      /* C staging pitch (floats) */

__device__ __forceinline__ void load_stage(
    uint32_t sb, int k0, int t,
    const __half* __restrict__ A, const __half* __restrict__ B,
    int m0, int n0, int K)
{
#pragma unroll
    for (int i = 0; i < 8; i++) {
        int idx = t + i * 256;          // 0..2047
        int arr = idx >> 10;            // 0:A 1:B
        int u   = idx & 1023;
        int row = u >> 3;               // 0..127
        int c   = u & 7;                // 16B chunk 0..7 (64 halves per row)
        const __half* base = arr ? B : A;
        int grow = (arr ? n0 : m0) + row;
        const __half* src = base + (size_t)grow * K + k0 + c * 8;
        uint32_t dst = sb + arr * ARR_BYTES + row * PITCHB + c * 16;
        CP_ASYNC16(dst, src);
    }
}

template <bool QKV_EPI>
__global__ void __launch_bounds__(256, 2) gemm_tc(
    const __half* __restrict__ A, const __half* __restrict__ B,
    const float* __restrict__ bias, float* __restrict__ C, int N, int K)
{
    extern __shared__ char dyn_smem[];
    const int t = threadIdx.x, wid = t >> 5, lane = t & 31;
    const int m0 = blockIdx.y * 128, n0 = blockIdx.x * 128;
    const int KT = K / BK;

    const uint32_t sbase = smem_u32(dyn_smem);
    const int wm = (wid >> 2) * 64;
    const int wn = (wid & 3) * 32;

    const int lmat = lane >> 3, lr = lane & 7;
    const uint32_t aOff = (uint32_t)((wm + (lmat & 1) * 8 + lr) * PITCHB + (lmat >> 1) * 16);
    const uint32_t bOff = (uint32_t)((wn + (lmat >> 1) * 8 + lr) * PITCHB + (lmat & 1) * 16);

    float acc[4][4][4];
#pragma unroll
    for (int i = 0; i < 4; i++)
#pragma unroll
        for (int j = 0; j < 4; j++)
#pragma unroll
            for (int r = 0; r < 4; r++) acc[i][j][r] = 0.f;

    load_stage(sbase + 0 * STG_BYTES, 0,  t, A, B, m0, n0, K);
    CP_COMMIT();
    load_stage(sbase + 1 * STG_BYTES, BK, t, A, B, m0, n0, K);
    CP_COMMIT();

    for (int kt = 0; kt < KT; kt++) {
        CP_WAIT1();
        __syncthreads();
        if (kt + 2 < KT)
            load_stage(sbase + ((kt + 2) % 3) * STG_BYTES, (kt + 2) * BK,
                       t, A, B, m0, n0, K);
        CP_COMMIT();

        const uint32_t sb = sbase + (kt % 3) * STG_BYTES;
#pragma unroll
        for (int ks = 0; ks < 4; ks++) {
            uint32_t ah[4][4], bh[2][4];
            const uint32_t kb = ks * 32;
#pragma unroll
            for (int mt = 0; mt < 4; mt++)
                LDSM4(ah[mt], sb + 0 * ARR_BYTES + aOff + mt * (16 * PITCHB) + kb);
#pragma unroll
            for (int j = 0; j < 2; j++)
                LDSM4(bh[j], sb + 1 * ARR_BYTES + bOff + j * (16 * PITCHB) + kb);
#pragma unroll
            for (int mt = 0; mt < 4; mt++)
#pragma unroll
                for (int nt = 0; nt < 4; nt++)
                    MMA16816(acc[mt][nt], ah[mt],
                             bh[nt >> 1][(nt & 1) * 2], bh[nt >> 1][(nt & 1) * 2 + 1]);
        }
    }
    CP_WAIT0();
    __syncthreads();

    const int g = lane >> 2, tg = lane & 3;

    if (!QKV_EPI) {
        float* Cs = (float*)dyn_smem;      // [128][CPITCH]
#pragma unroll
        for (int mt = 0; mt < 4; mt++)
#pragma unroll
            for (int nt = 0; nt < 4; nt++) {
                int r0 = wm + mt * 16 + g;
                int cc = wn + nt * 8 + tg * 2;
                Cs[r0 * CPITCH + cc]       = acc[mt][nt][0];
                Cs[r0 * CPITCH + cc + 1]   = acc[mt][nt][1];
                Cs[(r0 + 8) * CPITCH + cc]     = acc[mt][nt][2];
                Cs[(r0 + 8) * CPITCH + cc + 1] = acc[mt][nt][3];
            }
        __syncthreads();

        const int q = t & 31;
        const int rb = t >> 5;
        float4 bv = *(const float4*)(bias + n0 + q * 4);
#pragma unroll
        for (int i = 0; i < 16; i++) {
            int row = rb + i * 8;
            float4 v = *(const float4*)&Cs[row * CPITCH + q * 4];
            v.x += bv.x; v.y += bv.y; v.z += bv.z; v.w += bv.w;
            *(float4*)(C + (size_t)(m0 + row) * N + n0 + q * 4) = v;
        }
    } else {
        // fused QKV epilogue: bias + fp16 cvt + per-head scatter
        float* Cs = (float*)dyn_smem;      // [128][CPITCH]
        float bv[4][2];
#pragma unroll
        for (int nt = 0; nt < 4; nt++) {
            int gc = n0 + wn + nt * 8 + tg * 2;
            bv[nt][0] = bias[gc];
            bv[nt][1] = bias[gc + 1];
        }
#pragma unroll
        for (int mt = 0; mt < 4; mt++)
#pragma unroll
            for (int nt = 0; nt < 4; nt++) {
                int r0 = wm + mt * 16 + g;
                int cc = wn + nt * 8 + tg * 2;
                Cs[r0 * CPITCH + cc]       = acc[mt][nt][0] + bv[nt][0];
                Cs[r0 * CPITCH + cc + 1]   = acc[mt][nt][1] + bv[nt][1];
                Cs[(r0 + 8) * CPITCH + cc]     = acc[mt][nt][2] + bv[nt][0];
                Cs[(r0 + 8) * CPITCH + cc + 1] = acc[mt][nt][3] + bv[nt][1];
            }
        __syncthreads();

        const int b = m0 >> 11;
        const int sb0 = m0 & 2047;
        const int h0 = (n0 & 1023) >> 6;

        if (n0 < 2048) {
            // Q or K: [bh][s][64] row-major, fp16
            __half* Dh = (n0 < 1024) ? g_Qh : g_Kh;
            const int u = t & 63;
            const int h = h0 + (u >> 5);
            const int d0 = (u * 2) & 63;
            const int rofs = t >> 6;
#pragma unroll
            for (int p = 0; p < 32; p++) {
                int row = p * 4 + rofs;
                float v0 = Cs[row * CPITCH + 2 * u];
                float v1 = Cs[row * CPITCH + 2 * u + 1];
                size_t dst = ((size_t)(b * NHEADS + h) * SEQ + sb0 + row) * HD + d0;
                *(uint32_t*)(Dh + dst) = pack2(v0, v1);
            }
        } else {
            // V: transposed [bh][d][s], fp16
            const int w = t >> 5;
            const int l = t & 31;
#pragma unroll
            for (int i = 0; i < 16; i++) {
                int c = w * 16 + i;
                int h = h0 + (c >> 6);
                int d = c & 63;
#pragma unroll
                for (int qq = 0; qq < 2; qq++) {
                    int r = 2 * (l + 32 * qq);
                    float v0 = Cs[r * CPITCH + c];
                    float v1 = Cs[(r + 1) * CPITCH + c];
                    size_t dst = ((size_t)(b * NHEADS + h) * HD + d) * SEQ + sb0 + r;
                    *(uint32_t*)(g_Vth + dst) = pack2(v0, v1);
                }
            }
        }
    }
}

// ---------------------------------------------------------------------------
// Tensor-core flash attention.  QK f16-acc (2x rate), PV fp32-acc.
// Deferred-PV pipeline (single P buffer, R13-proven arithmetic).
// PAIRED tile groups: one cp.async group + one wait + one sync per 2 tiles.
// K ring 4, V ring 5.  Q tile 128, K/V tiles 64.
// Grid (SEQ/128, NHEADS, BATCH), 256 threads (8 warps), 2 CTAs/SM.
// ---------------------------------------------------------------------------
#define APB 144
#define QARR (128 * APB)                /* 18432 */
#define AARR (64 * APB)                 /* 9216 */
#define ATTN_SMEM (QARR + 4 * AARR + 5 * AARR)  /* 101376 */

__global__ void __launch_bounds__(256, 2) attn_tc(
    const __half* __restrict__ Qh,
    const __half* __restrict__ Kh,
    const __half* __restrict__ Vth)
{
    extern __shared__ char dyn_smem[];
    const int t = threadIdx.x, wid = t >> 5, lane = t & 31;
    const int qt = blockIdx.x, h = blockIdx.y, b = blockIdx.z;
    const int bh = b * NHEADS + h;
    const int q0 = qt * 128;

    const uint32_t sQh = smem_u32(dyn_smem);
    const uint32_t sK  = sQh + QARR;          // 4 buffers
    const uint32_t sV  = sK + 4 * AARR;       // 5 buffers

    const size_t qkBase = (size_t)bh * SEQ * HD;
    const size_t vBase  = (size_t)bh * HD * SEQ;

    // Q tile: 128 rows x 8 chunks = 1024 chunks
#pragma unroll
    for (int i = 0; i < 4; i++) {
        int idx = t + i * 256;
        int row = idx >> 3, ch = idx & 7;
        const __half* src = Qh + qkBase + (size_t)(q0 + row) * HD + ch * 8;
        CP_ASYNC16(sQh + row * APB + ch * 16, src);
    }
// tile j: K -> buf j%4, V -> buf j%5
#define LOAD_KV_TILE(j) do { \
    int kk0 = (j) * 64; \
    uint32_t kbuf = sK + ((j) % 4) * AARR; \
    uint32_t vbuf = sV + ((j) % 5) * AARR; \
    _Pragma("unroll") \
    for (int i = 0; i < 4; i++) { \
        int idx = t + i * 256; \
        int arr = idx >> 9; \
        int u = idx & 511, row = u >> 3, ch = u & 7; \
        const __half* src; uint32_t dbuf; \
        if (arr == 0) { src = Kh  + qkBase + (size_t)(kk0 + row) * HD + ch * 8; dbuf = kbuf; } \
        else          { src = Vth + vBase + (size_t)row * SEQ + kk0 + ch * 8; dbuf = vbuf; } \
        CP_ASYNC16(dbuf + row * APB + ch * 16, src); \
    } \
} while (0)

    // group 0: Q + tiles 0,1 ; group 1: tiles 2,3
    LOAD_KV_TILE(0);
    LOAD_KV_TILE(1);
    CP_COMMIT();
    LOAD_KV_TILE(2);
    LOAD_KV_TILE(3);
    CP_COMMIT();

    const int wm = wid * 16;
    const int lmat = lane >> 3, lr = lane & 7;
    const uint32_t aOff = (uint32_t)((wm + (lmat & 1) * 8 + lr) * APB + (lmat >> 1) * 16);
    const uint32_t bOff = (uint32_t)(((lmat >> 1) * 8 + lr) * APB + (lmat & 1) * 16);
    const int g = lane >> 2, tg = lane & 3;

    float O[8][4];
#pragma unroll
    for (int i = 0; i < 8; i++)
#pragma unroll
        for (int j = 0; j < 4; j++) O[i][j] = 0.f;
    float m0r = -1e30f, m1r = -1e30f, l0 = 0.f, l1 = 0.f;
    float c0p = 0.f, c1p = 0.f;          // pending O rescale factors
    uint32_t ph[16];                     // pending packed P (fp16)
    uint32_t Sh[16];                     // f16x2 QK accumulators

// compute S(f16) = Q K(kt)^T
#define QK_TILE(kt) do { \
    const uint32_t sKb = sK + ((kt) % 4) * AARR; \
    _Pragma("unroll") \
    for (int r = 0; r < 16; r++) Sh[r] = 0u; \
    _Pragma("unroll") \
    for (int kc = 0; kc < 4; kc++) { \
        uint32_t qh[4]; \
        LDSM4(qh, sQh + aOff + kc * 32); \
        _Pragma("unroll") \
        for (int j = 0; j < 4; j++) { \
            uint32_t kh[4]; \
            LDSM4(kh, sKb + j * (16 * APB) + bOff + kc * 32); \
            MMA16816H(&Sh[j * 4 + 0], qh, kh[0], kh[1]); \
            MMA16816H(&Sh[j * 4 + 2], qh, kh[2], kh[3]); \
        } \
    } \
} while (0)

// online softmax on Sh -> ph, c0p/c1p, m/l update
#define SOFTMAX_PACK() do { \
    float rmax0 = -1e30f, rmax1 = -1e30f; \
    _Pragma("unroll") \
    for (int r = 0; r < 16; r += 2) { \
        float2 a = h2f2(Sh[r]); \
        float2 bb = h2f2(Sh[r + 1]); \
        rmax0 = fmaxf(rmax0, fmaxf(a.x, a.y)); \
        rmax1 = fmaxf(rmax1, fmaxf(bb.x, bb.y)); \
    } \
    _Pragma("unroll") \
    for (int d = 1; d <= 2; d <<= 1) { \
        rmax0 = fmaxf(rmax0, __shfl_xor_sync(0xffffffffu, rmax0, d)); \
        rmax1 = fmaxf(rmax1, __shfl_xor_sync(0xffffffffu, rmax1, d)); \
    } \
    float mn0 = fmaxf(m0r, rmax0), mn1 = fmaxf(m1r, rmax1); \
    float ms0 = mn0 * SC, ms1 = mn1 * SC; \
    float sum0 = 0.f, sum1 = 0.f; \
    _Pragma("unroll") \
    for (int r = 0; r < 16; r += 2) { \
        float2 a = h2f2(Sh[r]); \
        float2 bb = h2f2(Sh[r + 1]); \
        float p0 = ex2(fmaf(a.x, SC, -ms0)); \
        float p1 = ex2(fmaf(a.y, SC, -ms0)); \
        float p2 = ex2(fmaf(bb.x, SC, -ms1)); \
        float p3 = ex2(fmaf(bb.y, SC, -ms1)); \
        sum0 += p0 + p1; \
        sum1 += p2 + p3; \
        ph[r] = pack2(p0, p1); \
        ph[r + 1] = pack2(p2, p3); \
    } \
    _Pragma("unroll") \
    for (int d = 1; d <= 2; d <<= 1) { \
        sum0 += __shfl_xor_sync(0xffffffffu, sum0, d); \
        sum1 += __shfl_xor_sync(0xffffffffu, sum1, d); \
    } \
    c0p = ex2(SC * (m0r - mn0)); \
    c1p = ex2(SC * (m1r - mn1)); \
    l0 = l0 * c0p + sum0; \
    l1 = l1 * c1p + sum1; \
    m0r = mn0; m1r = mn1; \
} while (0)

// O = O*c_pend + P(pend) * V(tile vj)   (fp32 accumulate)
#define RESCALE_PV(vj) do { \
    const uint32_t sVb = sV + ((vj) % 5) * AARR; \
    _Pragma("unroll") \
    for (int i = 0; i < 8; i++) { \
        O[i][0] *= c0p; O[i][1] *= c0p; \
        O[i][2] *= c1p; O[i][3] *= c1p; \
    } \
    _Pragma("unroll") \
    for (int kg = 0; kg < 4; kg++) { \
        _Pragma("unroll") \
        for (int dn = 0; dn < 4; dn++) { \
            uint32_t vh[4]; \
            LDSM4(vh, sVb + dn * (16 * APB) + bOff + kg * 32); \
            MMA16816(O[2 * dn],     &ph[kg * 4], vh[0], vh[1]); \
            MMA16816(O[2 * dn + 1], &ph[kg * 4], vh[2], vh[3]); \
        } \
    } \
} while (0)

    const int NKT = SEQ / 64;   /* 32 */
    const int NG  = NKT / 2;    /* 16 groups */

    // ---- group 0: tiles 0,1 ----
    CP_WAIT1();                 // group 0 (Q + tiles 0,1) complete
    __syncthreads();
    QK_TILE(0);
    SOFTMAX_PACK();
    QK_TILE(1);
    RESCALE_PV(0);
    SOFTMAX_PACK();

    // ---- groups 1..15: tiles 2g, 2g+1 ----
    for (int gg = 1; gg < NG; gg++) {
        CP_WAIT0();             // group gg complete
        __syncthreads();        // visibility + all done reading group gg-1
        if (gg + 1 < NG) {
            LOAD_KV_TILE(2 * gg + 2);
            LOAD_KV_TILE(2 * gg + 3);
        }
        CP_COMMIT();

        QK_TILE(2 * gg);
        RESCALE_PV(2 * gg - 1);
        SOFTMAX_PACK();

        QK_TILE(2 * gg + 1);
        RESCALE_PV(2 * gg);
        SOFTMAX_PACK();
    }

    // ---- epilogue: final pending PV (tile 31) ----
    RESCALE_PV(NKT - 1);

    float inv0 = 1.0f / l0, inv1 = 1.0f / l1;
    int r0 = b * SEQ + q0 + wm + g;
    int r1 = r0 + 8;
#pragma unroll
    for (int ot = 0; ot < 8; ot++) {
        int col = h * HD + ot * 8 + tg * 2;
        *(uint32_t*)(g_ch + (size_t)r0 * DMODEL + col) =
            pack2(O[ot][0] * inv0, O[ot][1] * inv0);
        *(uint32_t*)(g_ch + (size_t)r1 * DMODEL + col) =
            pack2(O[ot][2] * inv1, O[ot][3] * inv1);
    }
}

extern "C" void kernel_launch(void* const* d_in, const int* in_sizes, int n_in,
                              void* d_out, int out_size)
{
    const float* x     = (const float*)d_in[0];
    const float* qkv_w = (const float*)d_in[1];
    const float* qkv_b = (const float*)d_in[2];
    const float* out_w = (const float*)d_in[3];
    const float* out_b = (const float*)d_in[4];
    float* out = (float*)d_out;

    void *p_xh, *p_qwh, *p_owh, *p_ch, *p_Qh, *p_Kh, *p_Vth;
    cudaGetSymbolAddress(&p_xh, g_xh);
    cudaGetSymbolAddress(&p_qwh, g_qwh);
    cudaGetSymbolAddress(&p_owh, g_owh);
    cudaGetSymbolAddress(&p_ch, g_ch);
    cudaGetSymbolAddress(&p_Qh, g_Qh);
    cudaGetSymbolAddress(&p_Kh, g_Kh);
    cudaGetSymbolAddress(&p_Vth, g_Vth);

    cudaFuncSetAttribute(gemm_tc<false>, cudaFuncAttributeMaxDynamicSharedMemorySize,
                         GEMM_SMEM);
    cudaFuncSetAttribute(gemm_tc<true>, cudaFuncAttributeMaxDynamicSharedMemorySize,
                         GEMM_SMEM);
    cudaFuncSetAttribute(attn_tc, cudaFuncAttributeMaxDynamicSharedMemorySize,
                         ATTN_SMEM);

    // convert inputs to fp16
    {
        int n4 = ROWS * DMODEL / 4;
        cvt_kernel<<<(n4 + 255) / 256, 256>>>((const float4*)x, (uint2*)p_xh, n4);
        n4 = NQKV * DMODEL / 4;
        cvt_kernel<<<(n4 + 255) / 256, 256>>>((const float4*)qkv_w, (uint2*)p_qwh, n4);
        n4 = DMODEL * DMODEL / 4;
        cvt_kernel<<<(n4 + 255) / 256, 256>>>((const float4*)out_w, (uint2*)p_owh, n4);
    }

    // 1) QKV projection with fused per-head scatter epilogue
    gemm_tc<true><<<dim3(NQKV / 128, ROWS / 128), 256, GEMM_SMEM>>>(
        (const __half*)p_xh, (const __half*)p_qwh,
        qkv_b, nullptr, NQKV, DMODEL);

    // 2) tensor-core flash attention -> ctx (fp16)
    attn_tc<<<dim3(SEQ / 128, NHEADS, BATCH), 256, ATTN_SMEM>>>(
        (const __half*)p_Qh, (const __half*)p_Kh, (const __half*)p_Vth);

    // 3) output projection
    gemm_tc<false><<<dim3(DMODEL / 128, ROWS / 128), 256, GEMM_SMEM>>>(
        (const __half*)p_ch, (const __half*)p_owh,
        out_b, out, DMODEL, DMODEL);
}

// round 17
// speedup vs baseline: 1.0387x; 1.0379x over previous
#include <cuda_runtime.h>
#include <cuda_fp16.h>
#include <cstdint>
#include <math.h>

#define DMODEL 1024
#define NHEADS 16
#define HD 64
#define BATCH 4
#define SEQ 2048
#define ROWS (BATCH * SEQ)   /* 8192 */
#define NQKV (3 * DMODEL)    /* 3072 */

// softmax scale folded with log2(e) (base-2 softmax)
#define SC (0.125f * 1.44269504088896340736f)

// ---------------------------------------------------------------------------
// Scratch (allocation-free __device__ globals), fp16 operands
// ---------------------------------------------------------------------------
__device__ __align__(256) __half g_xh[(size_t)ROWS * DMODEL];        // x
__device__ __align__(256) __half g_qwh[(size_t)NQKV * DMODEL];       // qkv_w
__device__ __align__(256) __half g_owh[(size_t)DMODEL * DMODEL];     // out_w
__device__ __align__(256) __half g_ch[(size_t)ROWS * DMODEL];        // ctx
// per-head attention operands, written by fused QKV epilogue
__device__ __align__(256) __half g_Qh[(size_t)ROWS * DMODEL];        // Q [bh][s][64]
__device__ __align__(256) __half g_Kh[(size_t)ROWS * DMODEL];        // K [bh][s][64]
__device__ __align__(256) __half g_Vth[(size_t)ROWS * DMODEL];       // V^T [bh][d][s]

// ---------------------------------------------------------------------------
// helpers
// ---------------------------------------------------------------------------
__device__ __forceinline__ uint32_t smem_u32(const void* p) {
    return (uint32_t)__cvta_generic_to_shared(p);
}

__device__ __forceinline__ uint32_t pack2(float a, float b) {
    __half2 h = __floats2half2_rn(a, b);
    return *reinterpret_cast<uint32_t*>(&h);
}

__device__ __forceinline__ float2 h2f2(uint32_t u) {
    __half2 h = *reinterpret_cast<__half2*>(&u);
    return __half22float2(h);
}

__device__ __forceinline__ float ex2(float x) {
    float y;
    asm("ex2.approx.ftz.f32 %0, %1;" : "=f"(y) : "f"(x));
    return y;
}

#define LDSM4(r, addr) \
    asm volatile("ldmatrix.sync.aligned.m8n8.x4.shared.b16 {%0,%1,%2,%3}, [%4];" \
                 : "=r"((r)[0]), "=r"((r)[1]), "=r"((r)[2]), "=r"((r)[3]) : "r"(addr))

#define MMA16816(d, a, b0, b1) \
    asm volatile("mma.sync.aligned.m16n8k16.row.col.f32.f16.f16.f32 " \
                 "{%0,%1,%2,%3}, {%4,%5,%6,%7}, {%8,%9}, {%0,%1,%2,%3};" \
                 : "+f"((d)[0]), "+f"((d)[1]), "+f"((d)[2]), "+f"((d)[3]) \
                 : "r"((a)[0]), "r"((a)[1]), "r"((a)[2]), "r"((a)[3]), \
                   "r"(b0), "r"(b1))

// f16-accumulate MMA (double rate): D,C in 2 x b32 (4 halves)
#define MMA16816H(d, a, b0, b1) \
    asm volatile("mma.sync.aligned.m16n8k16.row.col.f16.f16.f16.f16 " \
                 "{%0,%1}, {%2,%3,%4,%5}, {%6,%7}, {%0,%1};" \
                 : "+r"((d)[0]), "+r"((d)[1]) \
                 : "r"((a)[0]), "r"((a)[1]), "r"((a)[2]), "r"((a)[3]), \
                   "r"(b0), "r"(b1))

#define CP_ASYNC16(dst, src) \
    asm volatile("cp.async.cg.shared.global [%0], [%1], 16;" :: "r"(dst), "l"(src))
#define CP_COMMIT() asm volatile("cp.async.commit_group;" ::: "memory")
#define CP_WAIT1()  asm volatile("cp.async.wait_group 1;" ::: "memory")
#define CP_WAIT0()  asm volatile("cp.async.wait_group 0;" ::: "memory")

// ---------------------------------------------------------------------------
// fused fp32 -> fp16 convert for x | qkv_w | out_w (single launch)
// ---------------------------------------------------------------------------
#define N4_X   (ROWS * DMODEL / 4)           /* 2097152 */
#define N4_QW  (NQKV * DMODEL / 4)           /*  786432 */
#define N4_OW  (DMODEL * DMODEL / 4)         /*  262144 */
#define N4_ALL (N4_X + N4_QW + N4_OW)

__global__ void cvt_all_kernel(const float4* __restrict__ x,
                               const float4* __restrict__ qw,
                               const float4* __restrict__ ow) {
    int i = blockIdx.x * blockDim.x + threadIdx.x;
    if (i >= N4_ALL) return;
    const float4* src;
    uint2* dst;
    int j;
    if (i < N4_X) {
        src = x;  dst = (uint2*)g_xh;  j = i;
    } else if (i < N4_X + N4_QW) {
        src = qw; dst = (uint2*)g_qwh; j = i - N4_X;
    } else {
        src = ow; dst = (uint2*)g_owh; j = i - N4_X - N4_QW;
    }
    float4 v = src[j];
    uint2 uh;
    uh.x = pack2(v.x, v.y);
    uh.y = pack2(v.z, v.w);
    dst[j] = uh;
}

// ---------------------------------------------------------------------------
// Tensor-core GEMM via mma.sync, pure fp16 operands, fp32 accumulate.
// C = A*B^T + bias.  BM=BN=128, BK=64 (one barrier per 64-k slab),
// 256 thr, warp tile 64x32, 3-stage cp.async pipeline, 2 CTAs/SM.
// QKV_EPI: write Q/K per-head fp16 and V transposed fp16.
// ---------------------------------------------------------------------------
#define BK 64
#define PITCHB 144                      /* 128B data + 16B pad, conflict-free */
#define ARR_BYTES (128 * PITCHB)        /* 18432 */
#define STG_BYTES (2 * ARR_BYTES)       /* 36864: A, B */
#define GEMM_SMEM (3 * STG_BYTES)       /* 110592 (>= epilogue 67584) */
#define CPITCH 132                      /* C staging pitch (floats) */

__device__ __forceinline__ void load_stage(
    uint32_t sb, int k0, int t,
    const __half* __restrict__ A, const __half* __restrict__ B,
    int m0, int n0, int K)
{
#pragma unroll
    for (int i = 0; i < 8; i++) {
        int idx = t + i * 256;          // 0..2047
        int arr = idx >> 10;            // 0:A 1:B
        int u   = idx & 1023;
        int row = u >> 3;               // 0..127
        int c   = u & 7;                // 16B chunk 0..7 (64 halves per row)
        const __half* base = arr ? B : A;
        int grow = (arr ? n0 : m0) + row;
        const __half* src = base + (size_t)grow * K + k0 + c * 8;
        uint32_t dst = sb + arr * ARR_BYTES + row * PITCHB + c * 16;
        CP_ASYNC16(dst, src);
    }
}

template <bool QKV_EPI>
__global__ void __launch_bounds__(256, 2) gemm_tc(
    const __half* __restrict__ A, const __half* __restrict__ B,
    const float* __restrict__ bias, float* __restrict__ C, int N, int K)
{
    extern __shared__ char dyn_smem[];
    const int t = threadIdx.x, wid = t >> 5, lane = t & 31;
    const int m0 = blockIdx.y * 128, n0 = blockIdx.x * 128;
    const int KT = K / BK;

    const uint32_t sbase = smem_u32(dyn_smem);
    const int wm = (wid >> 2) * 64;
    const int wn = (wid & 3) * 32;

    const int lmat = lane >> 3, lr = lane & 7;
    const uint32_t aOff = (uint32_t)((wm + (lmat & 1) * 8 + lr) * PITCHB + (lmat >> 1) * 16);
    const uint32_t bOff = (uint32_t)((wn + (lmat >> 1) * 8 + lr) * PITCHB + (lmat & 1) * 16);

    float acc[4][4][4];
#pragma unroll
    for (int i = 0; i < 4; i++)
#pragma unroll
        for (int j = 0; j < 4; j++)
#pragma unroll
            for (int r = 0; r < 4; r++) acc[i][j][r] = 0.f;

    load_stage(sbase + 0 * STG_BYTES, 0,  t, A, B, m0, n0, K);
    CP_COMMIT();
    load_stage(sbase + 1 * STG_BYTES, BK, t, A, B, m0, n0, K);
    CP_COMMIT();

    for (int kt = 0; kt < KT; kt++) {
        CP_WAIT1();
        __syncthreads();
        if (kt + 2 < KT)
            load_stage(sbase + ((kt + 2) % 3) * STG_BYTES, (kt + 2) * BK,
                       t, A, B, m0, n0, K);
        CP_COMMIT();

        const uint32_t sb = sbase + (kt % 3) * STG_BYTES;
#pragma unroll
        for (int ks = 0; ks < 4; ks++) {
            uint32_t ah[4][4], bh[2][4];
            const uint32_t kb = ks * 32;
#pragma unroll
            for (int mt = 0; mt < 4; mt++)
                LDSM4(ah[mt], sb + 0 * ARR_BYTES + aOff + mt * (16 * PITCHB) + kb);
#pragma unroll
            for (int j = 0; j < 2; j++)
                LDSM4(bh[j], sb + 1 * ARR_BYTES + bOff + j * (16 * PITCHB) + kb);
#pragma unroll
            for (int mt = 0; mt < 4; mt++)
#pragma unroll
                for (int nt = 0; nt < 4; nt++)
                    MMA16816(acc[mt][nt], ah[mt],
                             bh[nt >> 1][(nt & 1) * 2], bh[nt >> 1][(nt & 1) * 2 + 1]);
        }
    }
    CP_WAIT0();
    __syncthreads();

    const int g = lane >> 2, tg = lane & 3;

    if (!QKV_EPI) {
        float* Cs = (float*)dyn_smem;      // [128][CPITCH]
#pragma unroll
        for (int mt = 0; mt < 4; mt++)
#pragma unroll
            for (int nt = 0; nt < 4; nt++) {
                int r0 = wm + mt * 16 + g;
                int cc = wn + nt * 8 + tg * 2;
                Cs[r0 * CPITCH + cc]       = acc[mt][nt][0];
                Cs[r0 * CPITCH + cc + 1]   = acc[mt][nt][1];
                Cs[(r0 + 8) * CPITCH + cc]     = acc[mt][nt][2];
                Cs[(r0 + 8) * CPITCH + cc + 1] = acc[mt][nt][3];
            }
        __syncthreads();

        const int q = t & 31;
        const int rb = t >> 5;
        float4 bv = *(const float4*)(bias + n0 + q * 4);
#pragma unroll
        for (int i = 0; i < 16; i++) {
            int row = rb + i * 8;
            float4 v = *(const float4*)&Cs[row * CPITCH + q * 4];
            v.x += bv.x; v.y += bv.y; v.z += bv.z; v.w += bv.w;
            *(float4*)(C + (size_t)(m0 + row) * N + n0 + q * 4) = v;
        }
    } else {
        // fused QKV epilogue: bias + fp16 cvt + per-head scatter
        float* Cs = (float*)dyn_smem;      // [128][CPITCH]
        float bv[4][2];
#pragma unroll
        for (int nt = 0; nt < 4; nt++) {
            int gc = n0 + wn + nt * 8 + tg * 2;
            bv[nt][0] = bias[gc];
            bv[nt][1] = bias[gc + 1];
        }
#pragma unroll
        for (int mt = 0; mt < 4; mt++)
#pragma unroll
            for (int nt = 0; nt < 4; nt++) {
                int r0 = wm + mt * 16 + g;
                int cc = wn + nt * 8 + tg * 2;
                Cs[r0 * CPITCH + cc]       = acc[mt][nt][0] + bv[nt][0];
                Cs[r0 * CPITCH + cc + 1]   = acc[mt][nt][1] + bv[nt][1];
                Cs[(r0 + 8) * CPITCH + cc]     = acc[mt][nt][2] + bv[nt][0];
                Cs[(r0 + 8) * CPITCH + cc + 1] = acc[mt][nt][3] + bv[nt][1];
            }
        __syncthreads();

        const int b = m0 >> 11;
        const int sb0 = m0 & 2047;
        const int h0 = (n0 & 1023) >> 6;

        if (n0 < 2048) {
            // Q or K: [bh][s][64] row-major, fp16
            __half* Dh = (n0 < 1024) ? g_Qh : g_Kh;
            const int u = t & 63;
            const int h = h0 + (u >> 5);
            const int d0 = (u * 2) & 63;
            const int rofs = t >> 6;
#pragma unroll
            for (int p = 0; p < 32; p++) {
                int row = p * 4 + rofs;
                float v0 = Cs[row * CPITCH + 2 * u];
                float v1 = Cs[row * CPITCH + 2 * u + 1];
                size_t dst = ((size_t)(b * NHEADS + h) * SEQ + sb0 + row) * HD + d0;
                *(uint32_t*)(Dh + dst) = pack2(v0, v1);
            }
        } else {
            // V: transposed [bh][d][s], fp16
            const int w = t >> 5;
            const int l = t & 31;
#pragma unroll
            for (int i = 0; i < 16; i++) {
                int c = w * 16 + i;
                int h = h0 + (c >> 6);
                int d = c & 63;
#pragma unroll
                for (int qq = 0; qq < 2; qq++) {
                    int r = 2 * (l + 32 * qq);
                    float v0 = Cs[r * CPITCH + c];
                    float v1 = Cs[(r + 1) * CPITCH + c];
                    size_t dst = ((size_t)(b * NHEADS + h) * HD + d) * SEQ + sb0 + r;
                    *(uint32_t*)(g_Vth + dst) = pack2(v0, v1);
                }
            }
        }
    }
}

// ---------------------------------------------------------------------------
// Tensor-core flash attention.  QK f16-acc (2x rate), PV fp32-acc.
// Deferred-PV pipeline (R13 configuration — empirical optimum).
// Q tile 128, K/V tiles 64.  Grid (SEQ/128, NHEADS, BATCH), 256 threads
// (8 warps, 16 q-rows each), 2 CTAs/SM.  K ring 3, V ring 4.
// ---------------------------------------------------------------------------
#define APB 144
#define QARR (128 * APB)                /* 18432 */
#define AARR (64 * APB)                 /* 9216 */
#define ATTN_SMEM (QARR + 3 * AARR + 4 * AARR)  /* 82944 */

__global__ void __launch_bounds__(256, 2) attn_tc(
    const __half* __restrict__ Qh,
    const __half* __restrict__ Kh,
    const __half* __restrict__ Vth)
{
    extern __shared__ char dyn_smem[];
    const int t = threadIdx.x, wid = t >> 5, lane = t & 31;
    const int qt = blockIdx.x, h = blockIdx.y, b = blockIdx.z;
    const int bh = b * NHEADS + h;
    const int q0 = qt * 128;

    const uint32_t sQh = smem_u32(dyn_smem);
    const uint32_t sK  = sQh + QARR;          // 3 buffers
    const uint32_t sV  = sK + 3 * AARR;       // 4 buffers

    const size_t qkBase = (size_t)bh * SEQ * HD;
    const size_t vBase  = (size_t)bh * HD * SEQ;

    // Q tile: 128 rows x 8 chunks = 1024 chunks
#pragma unroll
    for (int i = 0; i < 4; i++) {
        int idx = t + i * 256;
        int row = idx >> 3, ch = idx & 7;
        const __half* src = Qh + qkBase + (size_t)(q0 + row) * HD + ch * 8;
        CP_ASYNC16(sQh + row * APB + ch * 16, src);
    }
// tile j: K -> buf j%3, V -> buf j%4
#define LOAD_KV_TILE(j) do { \
    int kk0 = (j) * 64; \
    uint32_t kbuf = sK + ((j) % 3) * AARR; \
    uint32_t vbuf = sV + ((j) % 4) * AARR; \
    _Pragma("unroll") \
    for (int i = 0; i < 4; i++) { \
        int idx = t + i * 256; \
        int arr = idx >> 9; \
        int u = idx & 511, row = u >> 3, ch = u & 7; \
        const __half* src; uint32_t dbuf; \
        if (arr == 0) { src = Kh  + qkBase + (size_t)(kk0 + row) * HD + ch * 8; dbuf = kbuf; } \
        else          { src = Vth + vBase + (size_t)row * SEQ + kk0 + ch * 8; dbuf = vbuf; } \
        CP_ASYNC16(dbuf + row * APB + ch * 16, src); \
    } \
} while (0)

    LOAD_KV_TILE(0);
    CP_COMMIT();
    LOAD_KV_TILE(1);
    CP_COMMIT();

    const int wm = wid * 16;
    const int lmat = lane >> 3, lr = lane & 7;
    const uint32_t aOff = (uint32_t)((wm + (lmat & 1) * 8 + lr) * APB + (lmat >> 1) * 16);
    const uint32_t bOff = (uint32_t)(((lmat >> 1) * 8 + lr) * APB + (lmat & 1) * 16);
    const int g = lane >> 2, tg = lane & 3;

    float O[8][4];
#pragma unroll
    for (int i = 0; i < 8; i++)
#pragma unroll
        for (int j = 0; j < 4; j++) O[i][j] = 0.f;
    float m0r = -1e30f, m1r = -1e30f, l0 = 0.f, l1 = 0.f;
    float c0p = 0.f, c1p = 0.f;          // pending O rescale factors
    uint32_t ph[16];                     // pending packed P (fp16)
    uint32_t Sh[16];                     // f16x2 QK accumulators

// compute S(f16) = Q K(kt)^T
#define QK_TILE(kt) do { \
    const uint32_t sKb = sK + ((kt) % 3) * AARR; \
    _Pragma("unroll") \
    for (int r = 0; r < 16; r++) Sh[r] = 0u; \
    _Pragma("unroll") \
    for (int kc = 0; kc < 4; kc++) { \
        uint32_t qh[4]; \
        LDSM4(qh, sQh + aOff + kc * 32); \
        _Pragma("unroll") \
        for (int j = 0; j < 4; j++) { \
            uint32_t kh[4]; \
            LDSM4(kh, sKb + j * (16 * APB) + bOff + kc * 32); \
            MMA16816H(&Sh[j * 4 + 0], qh, kh[0], kh[1]); \
            MMA16816H(&Sh[j * 4 + 2], qh, kh[2], kh[3]); \
        } \
    } \
} while (0)

// online softmax on Sh -> ph, c0p/c1p, m/l update
#define SOFTMAX_PACK() do { \
    float rmax0 = -1e30f, rmax1 = -1e30f; \
    _Pragma("unroll") \
    for (int r = 0; r < 16; r += 2) { \
        float2 a = h2f2(Sh[r]); \
        float2 bb = h2f2(Sh[r + 1]); \
        rmax0 = fmaxf(rmax0, fmaxf(a.x, a.y)); \
        rmax1 = fmaxf(rmax1, fmaxf(bb.x, bb.y)); \
    } \
    _Pragma("unroll") \
    for (int d = 1; d <= 2; d <<= 1) { \
        rmax0 = fmaxf(rmax0, __shfl_xor_sync(0xffffffffu, rmax0, d)); \
        rmax1 = fmaxf(rmax1, __shfl_xor_sync(0xffffffffu, rmax1, d)); \
    } \
    float mn0 = fmaxf(m0r, rmax0), mn1 = fmaxf(m1r, rmax1); \
    float ms0 = mn0 * SC, ms1 = mn1 * SC; \
    float sum0 = 0.f, sum1 = 0.f; \
    _Pragma("unroll") \
    for (int r = 0; r < 16; r += 2) { \
        float2 a = h2f2(Sh[r]); \
        float2 bb = h2f2(Sh[r + 1]); \
        float p0 = ex2(fmaf(a.x, SC, -ms0)); \
        float p1 = ex2(fmaf(a.y, SC, -ms0)); \
        float p2 = ex2(fmaf(bb.x, SC, -ms1)); \
        float p3 = ex2(fmaf(bb.y, SC, -ms1)); \
        sum0 += p0 + p1; \
        sum1 += p2 + p3; \
        ph[r] = pack2(p0, p1); \
        ph[r + 1] = pack2(p2, p3); \
    } \
    _Pragma("unroll") \
    for (int d = 1; d <= 2; d <<= 1) { \
        sum0 += __shfl_xor_sync(0xffffffffu, sum0, d); \
        sum1 += __shfl_xor_sync(0xffffffffu, sum1, d); \
    } \
    c0p = ex2(SC * (m0r - mn0)); \
    c1p = ex2(SC * (m1r - mn1)); \
    l0 = l0 * c0p + sum0; \
    l1 = l1 * c1p + sum1; \
    m0r = mn0; m1r = mn1; \
} while (0)

// O = O*c_pend + P(pend) * V(tile vj)   (fp32 accumulate)
#define RESCALE_PV(vj) do { \
    const uint32_t sVb = sV + ((vj) % 4) * AARR; \
    _Pragma("unroll") \
    for (int i = 0; i < 8; i++) { \
        O[i][0] *= c0p; O[i][1] *= c0p; \
        O[i][2] *= c1p; O[i][3] *= c1p; \
    } \
    _Pragma("unroll") \
    for (int kg = 0; kg < 4; kg++) { \
        _Pragma("unroll") \
        for (int dn = 0; dn < 4; dn++) { \
            uint32_t vh[4]; \
            LDSM4(vh, sVb + dn * (16 * APB) + bOff + kg * 32); \
            MMA16816(O[2 * dn],     &ph[kg * 4], vh[0], vh[1]); \
            MMA16816(O[2 * dn + 1], &ph[kg * 4], vh[2], vh[3]); \
        } \
    } \
} while (0)

    const int NKT = SEQ / 64;

    // ---- iteration 0: QK + softmax only (no PV yet) ----
    CP_WAIT1();
    __syncthreads();
    LOAD_KV_TILE(2);
    CP_COMMIT();
    QK_TILE(0);
    SOFTMAX_PACK();

    // ---- main loop: QK(kt) ; O*c + PV(kt-1) ; softmax(kt) ----
    for (int kt = 1; kt < NKT; kt++) {
        CP_WAIT1();
        __syncthreads();
        if (kt + 2 < NKT) {
            LOAD_KV_TILE(kt + 2);
        }
        CP_COMMIT();

        QK_TILE(kt);
        RESCALE_PV(kt - 1);
        SOFTMAX_PACK();
    }

    // ---- epilogue: final pending PV ----
    RESCALE_PV(NKT - 1);

    float inv0 = 1.0f / l0, inv1 = 1.0f / l1;
    int r0 = b * SEQ + q0 + wm + g;
    int r1 = r0 + 8;
#pragma unroll
    for (int ot = 0; ot < 8; ot++) {
        int col = h * HD + ot * 8 + tg * 2;
        *(uint32_t*)(g_ch + (size_t)r0 * DMODEL + col) =
            pack2(O[ot][0] * inv0, O[ot][1] * inv0);
        *(uint32_t*)(g_ch + (size_t)r1 * DMODEL + col) =
            pack2(O[ot][2] * inv1, O[ot][3] * inv1);
    }
}

extern "C" void kernel_launch(void* const* d_in, const int* in_sizes, int n_in,
                              void* d_out, int out_size)
{
    const float* x     = (const float*)d_in[0];
    const float* qkv_w = (const float*)d_in[1];
    const float* qkv_b = (const float*)d_in[2];
    const float* out_w = (const float*)d_in[3];
    const float* out_b = (const float*)d_in[4];
    float* out = (float*)d_out;

    void *p_xh, *p_qwh, *p_owh, *p_ch, *p_Qh, *p_Kh, *p_Vth;
    cudaGetSymbolAddress(&p_xh, g_xh);
    cudaGetSymbolAddress(&p_qwh, g_qwh);
    cudaGetSymbolAddress(&p_owh, g_owh);
    cudaGetSymbolAddress(&p_ch, g_ch);
    cudaGetSymbolAddress(&p_Qh, g_Qh);
    cudaGetSymbolAddress(&p_Kh, g_Kh);
    cudaGetSymbolAddress(&p_Vth, g_Vth);

    cudaFuncSetAttribute(gemm_tc<false>, cudaFuncAttributeMaxDynamicSharedMemorySize,
                         GEMM_SMEM);
    cudaFuncSetAttribute(gemm_tc<true>, cudaFuncAttributeMaxDynamicSharedMemorySize,
                         GEMM_SMEM);
    cudaFuncSetAttribute(attn_tc, cudaFuncAttributeMaxDynamicSharedMemorySize,
                         ATTN_SMEM);

    // 0) fused convert of all fp32 inputs to fp16 (single launch)
    cvt_all_kernel<<<(N4_ALL + 255) / 256, 256>>>(
        (const float4*)x, (const float4*)qkv_w, (const float4*)out_w);

    // 1) QKV projection with fused per-head scatter epilogue
    gemm_tc<true><<<dim3(NQKV / 128, ROWS / 128), 256, GEMM_SMEM>>>(
        (const __half*)p_xh, (const __half*)p_qwh,
        qkv_b, nullptr, NQKV, DMODEL);

    // 2) tensor-core flash attention -> ctx (fp16)
    attn_tc<<<dim3(SEQ / 128, NHEADS, BATCH), 256, ATTN_SMEM>>>(
        (const __half*)p_Qh, (const __half*)p_Kh, (const __half*)p_Vth);

    // 3) output projection
    gemm_tc<false><<<dim3(DMODEL / 128, ROWS / 128), 256, GEMM_SMEM>>>(
        (const __half*)p_ch, (const __half*)p_owh,
        out_b, out, DMODEL, DMODEL);
}